// round 3
// baseline (speedup 1.0000x reference)
#include <cuda_runtime.h>
#include <math.h>

#define NMAX 100000
#define EMAX 3200000

// Scratch (static device globals — no allocations allowed)
__device__ int   g_is64;             // 1 if edge_index buffer is int64, 0 if int32
__device__ int   g_src[EMAX];
__device__ int   g_dst[EMAX];
__device__ int   g_deg[NMAX];
__device__ float g_dinv[NMAX];
__device__ __align__(16) float g_t1[NMAX * 16];  // (x@W1)*dinv  (pre-scaled messages)
__device__ __align__(16) float g_a1[NMAX * 16];  // layer-1 accumulator
__device__ __align__(8)  float g_t2[NMAX * 2];   // (h@W2)*dinv
__device__ __align__(8)  float g_a2[NMAX * 2];   // layer-2 accumulator

__device__ __forceinline__ void red_add_v4(float* p, float4 v) {
    asm volatile("red.global.add.v4.f32 [%0], {%1,%2,%3,%4};"
                 :: "l"(p), "f"(v.x), "f"(v.y), "f"(v.z), "f"(v.w) : "memory");
}
__device__ __forceinline__ void red_add_v2(float* p, float2 v) {
    asm volatile("red.global.add.v2.f32 [%0], {%1,%2};"
                 :: "l"(p), "f"(v.x), "f"(v.y) : "memory");
}

// ---------------------------------------------------------------------------
// K_detect: decide whether the edge buffer holds int64 or int32.
__global__ void k_detect(const int* __restrict__ ei32) {
    if (threadIdx.x == 0 && blockIdx.x == 0) {
        int all0 = 1;
        for (int i = 0; i < 64; i++) {
            if (ei32[2 * i + 1] != 0) { all0 = 0; break; }
        }
        g_is64 = all0;
    }
}

// K0a: deg[i] = 1 (self loop)
__global__ void k_deg_init(int N) {
    int i = blockIdx.x * blockDim.x + threadIdx.x;
    if (i < N) g_deg[i] = 1;
}

// K0b: convert edge indices -> int32 arrays, count degrees on dst
__global__ void k_convert(const void* __restrict__ ei, int E, int N) {
    int e = blockIdx.x * blockDim.x + threadIdx.x;
    if (e >= E) return;
    int s, d;
    if (g_is64) {
        const long long* p = (const long long*)ei;
        s = (int)p[e];
        d = (int)p[(long long)E + e];
    } else {
        const int* p = (const int*)ei;
        s = p[e];
        d = p[E + e];
    }
    if ((unsigned)s >= (unsigned)N) s = 0;
    if ((unsigned)d >= (unsigned)N) d = 0;
    g_src[e] = s;
    g_dst[e] = d;
    atomicAdd(&g_deg[d], 1);
}

// ---------------------------------------------------------------------------
// K1: t1 = (x @ W1) * dinv ; a1 initialized with self-loop message t1
// (the epilogue multiplies the whole accumulator by dinv[dst], supplying the
//  second normalization factor for the self loop)
__global__ void k_gemm1(const float* __restrict__ x, const float* __restrict__ W1, int N) {
    __shared__ float w[128 * 16];
    for (int i = threadIdx.x; i < 128 * 16; i += blockDim.x) w[i] = W1[i];
    __syncthreads();

    int node = blockIdx.x * blockDim.x + threadIdx.x;
    if (node >= N) return;

    float acc[16];
#pragma unroll
    for (int j = 0; j < 16; j++) acc[j] = 0.0f;

    const float4* xr = (const float4*)(x + (size_t)node * 128);
#pragma unroll 4
    for (int k4 = 0; k4 < 32; k4++) {
        float4 v = xr[k4];
        int base = k4 * 4 * 16;
#pragma unroll
        for (int j = 0; j < 16; j++) {
            float s = acc[j];
            s = fmaf(v.x, w[base + j], s);
            s = fmaf(v.y, w[base + 16 + j], s);
            s = fmaf(v.z, w[base + 32 + j], s);
            s = fmaf(v.w, w[base + 48 + j], s);
            acc[j] = s;
        }
    }

    float d = rsqrtf((float)g_deg[node]);
    g_dinv[node] = d;

    float4* t1 = (float4*)&g_t1[node * 16];
    float4* a1 = (float4*)&g_a1[node * 16];
#pragma unroll
    for (int q = 0; q < 4; q++) {
        float4 t;
        t.x = acc[q * 4 + 0] * d;
        t.y = acc[q * 4 + 1] * d;
        t.z = acc[q * 4 + 2] * d;
        t.w = acc[q * 4 + 3] * d;
        t1[q] = t;
        a1[q] = t;   // self-loop message: t1 (NOT t1*d)
    }
}

// ---------------------------------------------------------------------------
// K2: layer-1 edge aggregation. 4 threads per edge, each handles 4 floats.
__global__ void k_edge1(int E) {
    int t = blockIdx.x * blockDim.x + threadIdx.x;
    int e = t >> 2;
    if (e >= E) return;
    int p = t & 3;
    int s = g_src[e];
    int d = g_dst[e];
    float4 v = *(const float4*)&g_t1[s * 16 + p * 4];
    red_add_v4(&g_a1[d * 16 + p * 4], v);
}

// ---------------------------------------------------------------------------
// K3: h = relu(dinv*a1 + b1); t2 = (h @ W2) * dinv ; a2 init = t2 (self loop)
__global__ void k_mid(const float* __restrict__ b1, const float* __restrict__ W2, int N) {
    __shared__ float w2[32];
    __shared__ float bb[16];
    if (threadIdx.x < 32) w2[threadIdx.x] = W2[threadIdx.x];
    if (threadIdx.x < 16) bb[threadIdx.x] = b1[threadIdx.x];
    __syncthreads();

    int node = blockIdx.x * blockDim.x + threadIdx.x;
    if (node >= N) return;

    float d = g_dinv[node];
    const float4* a1 = (const float4*)&g_a1[node * 16];
    float t0 = 0.0f, t1 = 0.0f;
#pragma unroll
    for (int q = 0; q < 4; q++) {
        float4 a = a1[q];
        float h0 = fmaxf(fmaf(a.x, d, bb[q * 4 + 0]), 0.0f);
        float h1 = fmaxf(fmaf(a.y, d, bb[q * 4 + 1]), 0.0f);
        float h2 = fmaxf(fmaf(a.z, d, bb[q * 4 + 2]), 0.0f);
        float h3 = fmaxf(fmaf(a.w, d, bb[q * 4 + 3]), 0.0f);
        t0 = fmaf(h0, w2[(q * 4 + 0) * 2 + 0], t0);
        t1 = fmaf(h0, w2[(q * 4 + 0) * 2 + 1], t1);
        t0 = fmaf(h1, w2[(q * 4 + 1) * 2 + 0], t0);
        t1 = fmaf(h1, w2[(q * 4 + 1) * 2 + 1], t1);
        t0 = fmaf(h2, w2[(q * 4 + 2) * 2 + 0], t0);
        t1 = fmaf(h2, w2[(q * 4 + 2) * 2 + 1], t1);
        t0 = fmaf(h3, w2[(q * 4 + 3) * 2 + 0], t0);
        t1 = fmaf(h3, w2[(q * 4 + 3) * 2 + 1], t1);
    }
    t0 *= d; t1 *= d;
    float2 t = make_float2(t0, t1);
    *(float2*)&g_t2[node * 2] = t;
    *(float2*)&g_a2[node * 2] = t;   // self-loop message: t2 (NOT t2*d)
}

// ---------------------------------------------------------------------------
// K4: layer-2 edge aggregation, 1 thread per edge.
__global__ void k_edge2(int E) {
    int e = blockIdx.x * blockDim.x + threadIdx.x;
    if (e >= E) return;
    int s = g_src[e];
    int d = g_dst[e];
    float2 v = *(const float2*)&g_t2[s * 2];
    red_add_v2(&g_a2[d * 2], v);
}

// ---------------------------------------------------------------------------
// K5: out = log_softmax(dinv*a2 + b2)
__global__ void k_final(const float* __restrict__ b2, float* __restrict__ out, int N) {
    int node = blockIdx.x * blockDim.x + threadIdx.x;
    if (node >= N) return;
    float d = g_dinv[node];
    float2 a = *(const float2*)&g_a2[node * 2];
    float v0 = fmaf(a.x, d, b2[0]);
    float v1 = fmaf(a.y, d, b2[1]);
    float m = fmaxf(v0, v1);
    float lse = m + logf(expf(v0 - m) + expf(v1 - m));
    float2 o = make_float2(v0 - lse, v1 - lse);
    *(float2*)&out[node * 2] = o;
}

// ---------------------------------------------------------------------------
extern "C" void kernel_launch(void* const* d_in, const int* in_sizes, int n_in,
                              void* d_out, int out_size) {
    const float* x  = (const float*)d_in[0];
    const void*  ei = d_in[1];
    const float* W1 = (const float*)d_in[2];
    const float* b1 = (const float*)d_in[3];
    const float* W2 = (const float*)d_in[4];
    const float* b2 = (const float*)d_in[5];
    float* out = (float*)d_out;

    int N = in_sizes[0] / 128;
    int E = in_sizes[1] / 2;

    const int T = 256;
    k_detect<<<1, 32>>>((const int*)ei);
    k_deg_init<<<(N + T - 1) / T, T>>>(N);
    k_convert<<<(E + T - 1) / T, T>>>(ei, E, N);
    k_gemm1<<<(N + T - 1) / T, T>>>(x, W1, N);
    {
        long long total = (long long)E * 4;
        int blocks = (int)((total + T - 1) / T);
        k_edge1<<<blocks, T>>>(E);
    }
    k_mid<<<(N + T - 1) / T, T>>>(b1, W2, N);
    k_edge2<<<(E + T - 1) / T, T>>>(E);
    k_final<<<(N + T - 1) / T, T>>>(b2, out, N);
}